// round 1
// baseline (speedup 1.0000x reference)
#include <cuda_runtime.h>
#include <cuda_bf16.h>

// upfirdn2d: up=2, pad=(2,1,2,1), filter = outer([1,3,3,1],[1,3,3,1])/64 * gain4
// Reduces to a 2-tap separable filter per output parity:
//   even o: (1*x[i-1] + 3*x[i]) / 4
//   odd  o: (3*x[i]   + x[i+1]) / 4     (i = o>>1, OOB -> 0)
// Input  (16,512,32,32) f32, Output (16,512,64,64) f32.

constexpr int H = 32;
constexpr int W = 32;
constexpr int SROWS = 34;          // 32 + 1 halo each side
constexpr int SSTRIDE = 35;        // odd stride -> row parity splits bank sets

__global__ __launch_bounds__(256)
void Blur_29068338659488_kernel(const float* __restrict__ x,
                                float* __restrict__ y) {
    __shared__ float s[SROWS * SSTRIDE];

    const int bc = blockIdx.x;          // batch*channel plane index
    const int tid = threadIdx.x;

    // Zero smem (halo must be 0; zero everything, it's cheap)
    #pragma unroll
    for (int idx = tid; idx < SROWS * SSTRIDE; idx += 256) s[idx] = 0.0f;
    __syncthreads();

    // Load the 32x32 plane: 1024 floats = 256 float4 loads, one per thread.
    {
        const float4* src = reinterpret_cast<const float4*>(x) + (size_t)bc * (H * W / 4);
        float4 v = src[tid];
        int r = tid >> 3;               // input row 0..31
        int c = (tid & 7) << 2;         // input col 0,4,...,28
        float* d = s + (r + 1) * SSTRIDE + (c + 1);
        d[0] = v.x; d[1] = v.y; d[2] = v.z; d[3] = v.w;
    }
    __syncthreads();

    float4* dst = reinterpret_cast<float4*>(y) + (size_t)bc * 1024;  // 64*64/4

    // 1024 output float4s per plane; 4 per thread.
    // f -> oy = f>>4 (0..63), quad col qx = f&15 (output cols 4qx..4qx+3).
    #pragma unroll
    for (int u = 0; u < 4; u++) {
        int f  = tid + u * 256;
        int oy = f >> 4;
        int qx = f & 15;
        int i   = oy >> 1;              // input row
        int odd = oy & 1;

        // smem rows: input row r lives at smem row r+1.
        // even oy: rows (i-1, i) weights (1,3); odd oy: rows (i, i+1) weights (3,1)
        const float* p0 = s + (i + odd) * SSTRIDE + 2 * qx;  // v[2qx-1] is smem col 2qx
        const float* p1 = p0 + SSTRIDE;
        float wa = odd ? 3.0f : 1.0f;
        float wb = odd ? 1.0f : 3.0f;

        // Vertically filtered values v[2qx-1 .. 2qx+2] (unscaled, carries factor 4)
        float v0 = wa * p0[0] + wb * p1[0];
        float v1 = wa * p0[1] + wb * p1[1];
        float v2 = wa * p0[2] + wb * p1[2];
        float v3 = wa * p0[3] + wb * p1[3];

        // Horizontal pass; fold both /4 factors into one *1/16.
        float4 o;
        o.x = (v0 + 3.0f * v1) * 0.0625f;   // even col, j=2qx
        o.y = (3.0f * v1 + v2) * 0.0625f;   // odd  col, j=2qx
        o.z = (v1 + 3.0f * v2) * 0.0625f;   // even col, j=2qx+1
        o.w = (3.0f * v2 + v3) * 0.0625f;   // odd  col, j=2qx+1

        dst[f] = o;
    }
}

extern "C" void kernel_launch(void* const* d_in, const int* in_sizes, int n_in,
                              void* d_out, int out_size) {
    const float* x = (const float*)d_in[0];
    float* y = (float*)d_out;
    int planes = in_sizes[0] / (H * W);   // 16*512 = 8192
    Blur_29068338659488_kernel<<<planes, 256>>>(x, y);
}

// round 2
// speedup vs baseline: 1.0344x; 1.0344x over previous
#include <cuda_runtime.h>
#include <cuda_bf16.h>

// upfirdn2d: up=2, pad=(2,1,2,1), filter = outer([1,3,3,1],[1,3,3,1])/64 * gain 4
// Per-parity 2-tap separable filter:
//   even o: (1*x[i-1] + 3*x[i]) / 4
//   odd  o: (3*x[i]   + x[i+1]) / 4     (i = o>>1, OOB -> 0)
// Input (16,512,32,32) f32 -> Output (16,512,64,64) f32.
//
// One CTA per plane. Each thread computes a 4-row x 4-col output block from a
// 4x4 input patch read once from smem (8 x LDS.64, conflict-free, stride 36).

constexpr int H = 32;
constexpr int W = 32;
constexpr int SSTRIDE = 36;        // even -> LDS.64 aligned; +36 rows shift banks by 4
constexpr int SROWS = 34;          // 32 + halo

__global__ __launch_bounds__(256)
void Blur_29068338659488_kernel(const float* __restrict__ x,
                                float* __restrict__ y) {
    __shared__ float s[SROWS * SSTRIDE];

    const int bc = blockIdx.x;
    const int tid = threadIdx.x;

    // Zero ONLY the halo cells actually read: row 0, row 33, col 0, col 33.
    if (tid < 136) {
        int r, c;
        if (tid < 72) { r = (tid < 36) ? 0 : 33; c = (tid < 36) ? tid : tid - 36; }
        else          { int t = tid - 72; r = (t & 31) + 1; c = (t < 32) ? 0 : 33; }
        s[r * SSTRIDE + c] = 0.0f;
    }

    // Load the 32x32 plane: one float4 per thread. Input row r -> smem row r+1,
    // input col c -> smem col c+1.
    {
        const float4* src = reinterpret_cast<const float4*>(x) + (size_t)bc * (H * W / 4);
        float4 v = src[tid];
        int r = tid >> 3;
        int c = (tid & 7) << 2;
        float* d = s + (r + 1) * SSTRIDE + (c + 1);
        d[0] = v.x; d[1] = v.y; d[2] = v.z; d[3] = v.w;
    }
    __syncthreads();

    // Thread -> output block: rows 4*br .. 4*br+3, float4-column qx.
    const int br = tid >> 4;        // 0..15
    const int qx = tid & 15;        // 0..15

    // Input patch: rows 2br-1..2br+2 (= smem rows 2br..2br+3),
    //              cols 2qx-1..2qx+2 (= smem cols 2qx..2qx+3).
    const float* base = s + 2 * br * SSTRIDE + 2 * qx;

    float2 a01 = *reinterpret_cast<const float2*>(base);
    float2 a23 = *reinterpret_cast<const float2*>(base + 2);
    float2 b01 = *reinterpret_cast<const float2*>(base + SSTRIDE);
    float2 b23 = *reinterpret_cast<const float2*>(base + SSTRIDE + 2);
    float2 c01 = *reinterpret_cast<const float2*>(base + 2 * SSTRIDE);
    float2 c23 = *reinterpret_cast<const float2*>(base + 2 * SSTRIDE + 2);
    float2 d01 = *reinterpret_cast<const float2*>(base + 3 * SSTRIDE);
    float2 d23 = *reinterpret_cast<const float2*>(base + 3 * SSTRIDE + 2);

    float a0 = a01.x, a1 = a01.y, a2 = a23.x, a3 = a23.y;
    float b0 = b01.x, b1 = b01.y, b2 = b23.x, b3 = b23.y;
    float c0 = c01.x, c1 = c01.y, c2 = c23.x, c3 = c23.y;
    float d0 = d01.x, d1 = d01.y, d2 = d23.x, d3 = d23.y;

    float4* dst = reinterpret_cast<float4*>(y) + (size_t)bc * 1024 + br * 64 + qx;

    // k=0 (oy=4br,   even, i=2br):   v = a + 3b
    // k=1 (oy=4br+1, odd,  i=2br):   v = 3b + c
    // k=2 (oy=4br+2, even, i=2br+1): v = b + 3c
    // k=3 (oy=4br+3, odd,  i=2br+1): v = 3c + d
    {
        float v0 = fmaf(3.0f, b0, a0), v1 = fmaf(3.0f, b1, a1);
        float v2 = fmaf(3.0f, b2, a2), v3 = fmaf(3.0f, b3, a3);
        float4 o;
        o.x = fmaf(3.0f, v1, v0) * 0.0625f;
        o.y = fmaf(3.0f, v1, v2) * 0.0625f;
        o.z = fmaf(3.0f, v2, v1) * 0.0625f;
        o.w = fmaf(3.0f, v2, v3) * 0.0625f;
        dst[0] = o;
    }
    {
        float v0 = fmaf(3.0f, b0, c0), v1 = fmaf(3.0f, b1, c1);
        float v2 = fmaf(3.0f, b2, c2), v3 = fmaf(3.0f, b3, c3);
        float4 o;
        o.x = fmaf(3.0f, v1, v0) * 0.0625f;
        o.y = fmaf(3.0f, v1, v2) * 0.0625f;
        o.z = fmaf(3.0f, v2, v1) * 0.0625f;
        o.w = fmaf(3.0f, v2, v3) * 0.0625f;
        dst[16] = o;
    }
    {
        float v0 = fmaf(3.0f, c0, b0), v1 = fmaf(3.0f, c1, b1);
        float v2 = fmaf(3.0f, c2, b2), v3 = fmaf(3.0f, c3, b3);
        float4 o;
        o.x = fmaf(3.0f, v1, v0) * 0.0625f;
        o.y = fmaf(3.0f, v1, v2) * 0.0625f;
        o.z = fmaf(3.0f, v2, v1) * 0.0625f;
        o.w = fmaf(3.0f, v2, v3) * 0.0625f;
        dst[32] = o;
    }
    {
        float v0 = fmaf(3.0f, c0, d0), v1 = fmaf(3.0f, c1, d1);
        float v2 = fmaf(3.0f, c2, d2), v3 = fmaf(3.0f, c3, d3);
        float4 o;
        o.x = fmaf(3.0f, v1, v0) * 0.0625f;
        o.y = fmaf(3.0f, v1, v2) * 0.0625f;
        o.z = fmaf(3.0f, v2, v1) * 0.0625f;
        o.w = fmaf(3.0f, v2, v3) * 0.0625f;
        dst[48] = o;
    }
}

extern "C" void kernel_launch(void* const* d_in, const int* in_sizes, int n_in,
                              void* d_out, int out_size) {
    const float* x = (const float*)d_in[0];
    float* y = (float*)d_out;
    int planes = in_sizes[0] / (H * W);   // 8192
    Blur_29068338659488_kernel<<<planes, 256>>>(x, y);
}